// round 8
// baseline (speedup 1.0000x reference)
#include <cuda_runtime.h>

#define IN_FEATURES 212445
#define N1 65536
#define N2 16384
#define NBINS 128
#define NCLS 20
#define BATCH 32

#define ACC_THREADS 64
#define ACC_CHUNKS 28
#define NGROUPS ((IN_FEATURES + 3) / 4)   // 53112 groups of 4 features

#define QBLOCKS 64
#define QTHREADS 1024

#define FCHUNKS 8                          // fold: c3 chunks of 16
#define ACC_BLOCKS (ACC_CHUNKS * BATCH)    // 896
#define TOTAL_BLOCKS (ACC_BLOCKS + FCHUNKS * NCLS)  // 1056

// ---------------- device scratch (no allocation allowed) ----------------
__device__ float g_t2[BATCH * NBINS];            // zeroed by q_kernel each call
__device__ unsigned char g_q[N1 + 4];            // q[j] = p2[p1[j]]
__device__ unsigned int g_m8[NGROUPS];           // composed map, 4 bins packed/uint
__device__ float g_pcc1[QBLOCKS * NBINS];        // per-block cc1 partials
__device__ float g_pcnt2[QBLOCKS * NBINS];       // per-block cnt2 partials
__device__ float g_cc1[NBINS], g_cnt2[NBINS];    // finalized histograms
__device__ float g_A[128], g_B[128], g_C[128];   // folded weight vectors
__device__ float g_G[NCLS * NBINS];              // folded FC weights (atomic accum)
__device__ float g_K[NCLS];                      // folded constants (atomic accum)
__device__ unsigned int g_done;                  // accum completion counter

// ---------------- K1: q table + histograms + zero scratch + fold weights ----------------
__global__ void __launch_bounds__(QTHREADS) q_kernel(const int* __restrict__ p1,
                                                     const int* __restrict__ p2,
                                                     const float* __restrict__ W0,
                                                     const float* __restrict__ b0,
                                                     const float* __restrict__ W1,
                                                     const float* __restrict__ b1,
                                                     const float* __restrict__ W2,
                                                     const float* __restrict__ fcb) {
    int t = threadIdx.x;
    if (blockIdx.x == QBLOCKS) {
        // fold weights: u = W1@W0, v = W1@b0; A = W2@u, B = W2@v, C = W2@b1
        __shared__ float u[64], v[64];
        if (t < 64) {
            float su = 0.f, sv = 0.f;
            #pragma unroll 8
            for (int c = 0; c < 32; c++) {
                float w = W1[t * 32 + c];
                su += w * W0[c];
                sv += w * b0[c];
            }
            u[t] = su; v[t] = sv;
        }
        __syncthreads();
        if (t < 128) {
            float sa = 0.f, sb = 0.f, sc = 0.f;
            #pragma unroll 8
            for (int c2 = 0; c2 < 64; c2++) {
                float w = W2[t * 64 + c2];
                sa += w * u[c2]; sb += w * v[c2]; sc += w * b1[c2];
            }
            g_A[t] = sa; g_B[t] = sb; g_C[t] = sc;
        }
        // zero ALL of G (stride loop); seed K with fcb; reset done counter
        for (int i = t; i < NCLS * NBINS; i += QTHREADS) g_G[i] = 0.f;
        if (t < NCLS) g_K[t] = fcb[t];
        if (t == 0) g_done = 0u;
        return;
    }

    __shared__ float s_cc1[NBINS], s_cnt2[NBINS];
    int gid = blockIdx.x * QTHREADS + t;
    if (t < NBINS) { s_cc1[t] = 0.f; s_cnt2[t] = 0.f; }
    __syncthreads();

    // q[j] = p2[p1[j]]; cc1 histogram is histogram of q itself
    int m = p2[p1[gid]];
    g_q[gid] = (unsigned char)m;
    atomicAdd(&s_cc1[m], 1.0f);

    // cnt2 histogram over p2
    if (gid < N2) atomicAdd(&s_cnt2[p2[gid]], 1.0f);

    // zero t2
    if (gid < BATCH * NBINS) g_t2[gid] = 0.f;

    __syncthreads();
    if (t < NBINS) {
        g_pcc1[blockIdx.x * NBINS + t] = s_cc1[t];
        g_pcnt2[blockIdx.x * NBINS + t] = s_cnt2[t];
    }
}

// ---------------- K2: compose map m8[i] = q[p0[i]]; block 0 finalizes histograms ----------------
__global__ void __launch_bounds__(256) compose_kernel(const int* __restrict__ p0) {
    int t = threadIdx.x;
    if (blockIdx.x == 0 && t < NBINS) {
        float c1 = 0.f, c2 = 0.f;
        #pragma unroll 16
        for (int b = 0; b < QBLOCKS; b++) {
            c1 += g_pcc1[b * NBINS + t];
            c2 += g_pcnt2[b * NBINS + t];
        }
        g_cc1[t] = c1;
        g_cnt2[t] = c2;
    }
    int gid = blockIdx.x * 256 + t;
    if (gid >= NGROUPS) return;
    int base = gid * 4;
    unsigned int pack;
    if (base + 3 < IN_FEATURES) {
        int4 a = ((const int4*)p0)[gid];
        unsigned int m0 = g_q[a.x], m1 = g_q[a.y], m2 = g_q[a.z], m3 = g_q[a.w];
        pack = m0 | (m1 << 8) | (m2 << 16) | (m3 << 24);
    } else {
        pack = 0;
        for (int c = 0; c < 4; c++)
            if (base + c < IN_FEATURES)
                pack |= ((unsigned int)g_q[p0[base + c]]) << (8 * c);
    }
    g_m8[gid] = pack;
}

// ---------------- K3: accum + fcw fold + last-block logits ----------------
__global__ void __launch_bounds__(ACC_THREADS) accum_kernel(const float* __restrict__ x,
                                                            const float* __restrict__ b2,
                                                            const float* __restrict__ fcw,
                                                            float* __restrict__ out) {
    __shared__ float bins[NBINS * ACC_THREADS];  // 32 KB (reused by tail)
    __shared__ int s_last;
    int t = threadIdx.x;
    int bx = blockIdx.x;

    if (bx >= ACC_BLOCKS) {
        // ---- fcw fold block: (chunk, cls), 16 c3 rows, 64 threads x 2 m-values ----
        int fb = bx - ACC_BLOCKS;
        int chunk = fb % FCHUNKS;
        int cls = fb / FCHUNKS;
        int c3_0 = chunk * 16;
        int m0 = t, m1 = t + 64;

        float pG0 = 0.f, pG1 = 0.f, pB0 = 0.f, pB1 = 0.f;
        float pC0 = 0.f, pC1 = 0.f, pD = 0.f;
        const float* fr = fcw + (size_t)cls * (128 * NBINS) + (size_t)c3_0 * NBINS;
        #pragma unroll
        for (int i = 0; i < 16; i++) {
            float w0 = fr[i * NBINS + m0];
            float w1 = fr[i * NBINS + m1];
            int c3 = c3_0 + i;
            float A = g_A[c3], B = g_B[c3], C = g_C[c3];
            pG0 += w0 * A; pG1 += w1 * A;
            pB0 += w0 * B; pB1 += w1 * B;
            pC0 += w0 * C; pC1 += w1 * C;
            pD += (w0 + w1) * b2[c3];
        }
        atomicAdd(&g_G[cls * NBINS + m0], pG0);
        atomicAdd(&g_G[cls * NBINS + m1], pG1);

        float kpart = pB0 * g_cc1[m0] + pB1 * g_cc1[m1]
                    + pC0 * g_cnt2[m0] + pC1 * g_cnt2[m1] + pD;
        bins[t] = kpart;
        __syncthreads();
        #pragma unroll
        for (int s = 32; s > 0; s >>= 1) {
            if (t < s) bins[t] += bins[t + s];
            __syncthreads();
        }
        if (t == 0) atomicAdd(&g_K[cls], bins[0]);
    } else {
        // ---- accum block ----
        int c = bx % ACC_CHUNKS;
        int r = bx / ACC_CHUNKS;
        #pragma unroll
        for (int b = 0; b < NBINS; b++) bins[b * ACC_THREADS + t] = 0.f;

        const float* xr = x + (size_t)r * IN_FEATURES;
        int p = (4 - (r & 3)) & 3;                 // alignment phase (IN%4==1)
        int Kv = (IN_FEATURES - p) >> 2;
        int ck = (Kv + ACC_CHUNKS - 1) / ACC_CHUNKS;
        int k0 = c * ck;
        int k1 = min(k0 + ck, Kv);

        const unsigned int* mu = g_m8;
        const float4* xv = (const float4*)(xr + p);
        int sh = 8 * p;

        for (int k = k0 + t; k < k1; k += ACC_THREADS) {
            unsigned int u0 = mu[k];
            unsigned int u1 = mu[k + 1];
            unsigned int b = __funnelshift_r(u0, u1, sh);
            float4 X = xv[k];
            bins[(int)(b & 255u)         * ACC_THREADS + t] += X.x;
            bins[(int)((b >> 8) & 255u)  * ACC_THREADS + t] += X.y;
            bins[(int)((b >> 16) & 255u) * ACC_THREADS + t] += X.z;
            bins[(int)(b >> 24)          * ACC_THREADS + t] += X.w;
        }

        const unsigned char* m8b = (const unsigned char*)g_m8;
        if (c == 0 && t < p) {
            bins[(int)m8b[t] * ACC_THREADS + t] += xr[t];
        }
        int tail0 = p + 4 * Kv;
        int ntail = IN_FEATURES - tail0;
        if (c == ACC_CHUNKS - 1 && t < ntail) {
            bins[(int)m8b[tail0 + t] * ACC_THREADS + t] += xr[tail0 + t];
        }
        __syncthreads();

        for (int b = t; b < NBINS; b += ACC_THREADS) {
            float s = 0.f;
            #pragma unroll 8
            for (int l = 0; l < ACC_THREADS; l++) {
                int lc = (l + t) & (ACC_THREADS - 1);
                s += bins[b * ACC_THREADS + lc];
            }
            atomicAdd(&g_t2[r * NBINS + b], s);
        }
    }

    // ---- completion handshake; last block computes logits ----
    __syncthreads();
    if (t == 0) {
        __threadfence();
        unsigned int ticket = atomicAdd(&g_done, 1u);
        s_last = (ticket == TOTAL_BLOCKS - 1u) ? 1 : 0;
    }
    __syncthreads();
    if (!s_last) return;
    __threadfence();   // gpu-scope: invalidates L1, orders after observing all arrivals

    // stage G, t2 (transposed, pad 129 -> conflict-free), K into smem (reuse bins)
    float* sG  = bins;                    // 2560 floats
    float* st2 = bins + NCLS * NBINS;     // 32*129 = 4128 floats
    float* sK  = st2 + BATCH * 129;       // 20 floats
    for (int i = t; i < NCLS * NBINS; i += ACC_THREADS) sG[i] = __ldcg(&g_G[i]);
    for (int i = t; i < BATCH * NBINS; i += ACC_THREADS) {
        int n = i >> 7, m = i & 127;
        st2[n * 129 + m] = __ldcg(&g_t2[i]);
    }
    if (t < NCLS) sK[t] = __ldcg(&g_K[t]);
    __syncthreads();

    // thread t: n = t&31, cls = (t>>5) + 2j for j in 0..9
    int n = t & 31, cb = t >> 5;
    float acc[10];
    #pragma unroll
    for (int j = 0; j < 10; j++) acc[j] = sK[cb + 2 * j];
    for (int m = 0; m < NBINS; m++) {
        float v = st2[n * 129 + m];
        #pragma unroll
        for (int j = 0; j < 10; j++)
            acc[j] += sG[(cb + 2 * j) * NBINS + m] * v;
    }
    #pragma unroll
    for (int j = 0; j < 10; j++)
        out[n * NCLS + cb + 2 * j] = acc[j];
}

// ---------------- launch ----------------
extern "C" void kernel_launch(void* const* d_in, const int* in_sizes, int n_in,
                              void* d_out, int out_size) {
    const float* x   = (const float*)d_in[0];
    const float* W0  = (const float*)d_in[1];
    const float* b0  = (const float*)d_in[2];
    const float* W1  = (const float*)d_in[3];
    const float* b1  = (const float*)d_in[4];
    const float* W2  = (const float*)d_in[5];
    const float* b2  = (const float*)d_in[6];
    const float* fcw = (const float*)d_in[7];
    const float* fcb = (const float*)d_in[8];
    const int*   p0  = (const int*)d_in[9];
    const int*   p1  = (const int*)d_in[10];
    const int*   p2  = (const int*)d_in[11];
    float* out = (float*)d_out;

    q_kernel<<<QBLOCKS + 1, QTHREADS>>>(p1, p2, W0, b0, W1, b1, W2, fcb);
    compose_kernel<<<(NGROUPS + 255) / 256, 256>>>(p0);
    accum_kernel<<<TOTAL_BLOCKS, ACC_THREADS>>>(x, b2, fcw, out);
}

// round 9
// speedup vs baseline: 1.1404x; 1.1404x over previous
#include <cuda_runtime.h>

#define IN_FEATURES 212445
#define N1 65536
#define N2 16384
#define NBINS 128
#define NCLS 20
#define BATCH 32

#define ACC_THREADS 64
#define ACC_CHUNKS 28
#define NGROUPS ((IN_FEATURES + 3) / 4)   // 53112 groups of 4 features

#define QB 128
#define QT 512

#define CB ((NGROUPS + 255) / 256)        // 208 compose blocks
#define FCHUNKS 8
#define FOLD_BLOCKS (FCHUNKS * NCLS)      // 160

// ---------------- device scratch (no allocation allowed) ----------------
// contiguous zero block: [G (20*128)] [cc1 (128)] [cnt2 (128)]
__device__ float g_zero[NCLS * NBINS + 2 * NBINS];
#define G_G    (g_zero)
#define G_CC1  (g_zero + NCLS * NBINS)
#define G_CNT2 (g_zero + NCLS * NBINS + NBINS)

__device__ unsigned char g_q[N1 + 4];            // q[j] = p2[p1[j]]
__device__ unsigned int g_m8[NGROUPS];           // composed map, 4 bins packed/uint
__device__ float g_A[128], g_B[128], g_C[128];   // folded weight vectors

// ---------------- K1: q table + histograms (global atomics) + A/B/C + seed out ----------------
__global__ void __launch_bounds__(QT) q_kernel(const int* __restrict__ p1,
                                               const int* __restrict__ p2,
                                               const float* __restrict__ W0,
                                               const float* __restrict__ b0,
                                               const float* __restrict__ W1,
                                               const float* __restrict__ b1,
                                               const float* __restrict__ W2,
                                               const float* __restrict__ fcb,
                                               float* __restrict__ out) {
    int t = threadIdx.x;
    if (blockIdx.x == QB) {
        // fold weights: u = W1@W0, v = W1@b0; A = W2@u, B = W2@v, C = W2@b1
        __shared__ float u[64], v[64];
        if (t < 64) {
            float su = 0.f, sv = 0.f;
            #pragma unroll 8
            for (int c = 0; c < 32; c++) {
                float w = W1[t * 32 + c];
                su += w * W0[c];
                sv += w * b0[c];
            }
            u[t] = su; v[t] = sv;
        }
        __syncthreads();
        if (t < 128) {
            float sa = 0.f, sb = 0.f, sc = 0.f;
            #pragma unroll 8
            for (int c2 = 0; c2 < 64; c2++) {
                float w = W2[t * 64 + c2];
                sa += w * u[c2]; sb += w * v[c2]; sc += w * b1[c2];
            }
            g_A[t] = sa; g_B[t] = sb; g_C[t] = sc;
        }
        // seed out with fcb (atomics accumulate onto this)
        for (int i = t; i < BATCH * NCLS; i += QT) out[i] = fcb[i % NCLS];
        return;
    }

    __shared__ float s_cc1[NBINS], s_cnt2[NBINS];
    int gid = blockIdx.x * QT + t;
    if (t < NBINS) { s_cc1[t] = 0.f; s_cnt2[t] = 0.f; }
    __syncthreads();

    // q[j] = p2[p1[j]]; cc1 = histogram of q; cnt2 = histogram of p2
    int m = p2[p1[gid]];
    g_q[gid] = (unsigned char)m;
    atomicAdd(&s_cc1[m], 1.0f);
    if (gid < N2) atomicAdd(&s_cnt2[p2[gid]], 1.0f);

    __syncthreads();
    if (t < NBINS) {
        if (s_cc1[t] != 0.f)  atomicAdd(&G_CC1[t], s_cc1[t]);
        if (s_cnt2[t] != 0.f) atomicAdd(&G_CNT2[t], s_cnt2[t]);
    }
}

// ---------------- K2: compose (blocks [0,CB)) + fcw fold (blocks [CB,CB+160)) ----------------
__global__ void __launch_bounds__(256) compose_kernel(const int* __restrict__ p0,
                                                      const float* __restrict__ b2,
                                                      const float* __restrict__ fcw,
                                                      float* __restrict__ out) {
    int t = threadIdx.x;
    int bx = blockIdx.x;

    if (bx >= CB) {
        // ---- fold block: (chunk, cls); 256 threads = 128 m x 2 c3-halves of 8 ----
        __shared__ float red[256];
        int fb = bx - CB;
        int chunk = fb & (FCHUNKS - 1);
        int cls = fb >> 3;
        int m = t & 127;
        int half = t >> 7;
        int c3_0 = chunk * 16 + half * 8;

        float pG = 0.f, pB = 0.f, pC = 0.f, pD = 0.f;
        const float* fr = fcw + (size_t)cls * (128 * NBINS) + (size_t)c3_0 * NBINS + m;
        #pragma unroll
        for (int i = 0; i < 8; i++) {
            float w = fr[i * NBINS];
            int c3 = c3_0 + i;
            pG += w * g_A[c3];
            pB += w * g_B[c3];
            pC += w * g_C[c3];
            pD += w * b2[c3];
        }
        atomicAdd(&G_G[cls * NBINS + m], pG);

        red[t] = pB * G_CC1[m] + pC * G_CNT2[m] + pD;
        __syncthreads();
        #pragma unroll
        for (int s = 128; s > 0; s >>= 1) {
            if (t < s) red[t] += red[t + s];
            __syncthreads();
        }
        // add this (cls,chunk)'s K-contribution to every batch row
        if (t < BATCH) atomicAdd(&out[t * NCLS + cls], red[0]);
        return;
    }

    // ---- compose block: m8[i] = q[p0[i]] ----
    int gid = bx * 256 + t;
    if (gid >= NGROUPS) return;
    int base = gid * 4;
    unsigned int pack;
    if (base + 3 < IN_FEATURES) {
        int4 a = ((const int4*)p0)[gid];
        unsigned int m0 = g_q[a.x], m1 = g_q[a.y], m2 = g_q[a.z], m3 = g_q[a.w];
        pack = m0 | (m1 << 8) | (m2 << 16) | (m3 << 24);
    } else {
        pack = 0;
        for (int c = 0; c < 4; c++)
            if (base + c < IN_FEATURES)
                pack |= ((unsigned int)g_q[p0[base + c]]) << (8 * c);
    }
    g_m8[gid] = pack;
}

// ---------------- K3: accum + per-block logits contribution ----------------
__global__ void __launch_bounds__(ACC_THREADS) accum_kernel(const float* __restrict__ x,
                                                            float* __restrict__ out) {
    __shared__ float bins[NBINS * ACC_THREADS];  // 32 KB
    int t = threadIdx.x;
    int c = blockIdx.x % ACC_CHUNKS;
    int r = blockIdx.x / ACC_CHUNKS;
    #pragma unroll
    for (int b = 0; b < NBINS; b++) bins[b * ACC_THREADS + t] = 0.f;

    const float* xr = x + (size_t)r * IN_FEATURES;
    int p = (4 - (r & 3)) & 3;                 // alignment phase (IN%4==1)
    int Kv = (IN_FEATURES - p) >> 2;
    int ck = (Kv + ACC_CHUNKS - 1) / ACC_CHUNKS;
    int k0 = c * ck;
    int k1 = min(k0 + ck, Kv);

    const unsigned int* mu = g_m8;
    const float4* xv = (const float4*)(xr + p);
    int sh = 8 * p;

    for (int k = k0 + t; k < k1; k += ACC_THREADS) {
        unsigned int u0 = mu[k];
        unsigned int u1 = mu[k + 1];
        unsigned int b = __funnelshift_r(u0, u1, sh);
        float4 X = xv[k];
        bins[(int)(b & 255u)         * ACC_THREADS + t] += X.x;
        bins[(int)((b >> 8) & 255u)  * ACC_THREADS + t] += X.y;
        bins[(int)((b >> 16) & 255u) * ACC_THREADS + t] += X.z;
        bins[(int)(b >> 24)          * ACC_THREADS + t] += X.w;
    }

    const unsigned char* m8b = (const unsigned char*)g_m8;
    if (c == 0 && t < p) {
        bins[(int)m8b[t] * ACC_THREADS + t] += xr[t];
    }
    int tail0 = p + 4 * Kv;
    int ntail = IN_FEATURES - tail0;
    if (c == ACC_CHUNKS - 1 && t < ntail) {
        bins[(int)m8b[tail0 + t] * ACC_THREADS + t] += xr[tail0 + t];
    }
    __syncthreads();

    // reduce 64 private columns: thread t owns bins t and t+64
    float s0 = 0.f, s1 = 0.f;
    #pragma unroll 8
    for (int l = 0; l < ACC_THREADS; l++) {
        int lc = (l + t) & (ACC_THREADS - 1);
        s0 += bins[t * ACC_THREADS + lc];
        s1 += bins[(t + 64) * ACC_THREADS + lc];
    }

    // dot against G per class, warp-reduce, atomicAdd into out
    int lid = t & 31;
    #pragma unroll
    for (int cls = 0; cls < NCLS; cls++) {
        float a = G_G[cls * NBINS + t] * s0 + G_G[cls * NBINS + t + 64] * s1;
        #pragma unroll
        for (int off = 16; off > 0; off >>= 1)
            a += __shfl_xor_sync(0xFFFFFFFFu, a, off);
        if (lid == 0) atomicAdd(&out[r * NCLS + cls], a);
    }
}

// ---------------- launch ----------------
extern "C" void kernel_launch(void* const* d_in, const int* in_sizes, int n_in,
                              void* d_out, int out_size) {
    const float* x   = (const float*)d_in[0];
    const float* W0  = (const float*)d_in[1];
    const float* b0  = (const float*)d_in[2];
    const float* W1  = (const float*)d_in[3];
    const float* b1  = (const float*)d_in[4];
    const float* W2  = (const float*)d_in[5];
    const float* b2  = (const float*)d_in[6];
    const float* fcw = (const float*)d_in[7];
    const float* fcb = (const float*)d_in[8];
    const int*   p0  = (const int*)d_in[9];
    const int*   p1  = (const int*)d_in[10];
    const int*   p2  = (const int*)d_in[11];
    float* out = (float*)d_out;

    void* zp = nullptr;
    cudaGetSymbolAddress(&zp, g_zero);
    cudaMemsetAsync(zp, 0, sizeof(float) * (NCLS * NBINS + 2 * NBINS));

    q_kernel<<<QB + 1, QT>>>(p1, p2, W0, b0, W1, b1, W2, fcb, out);
    compose_kernel<<<CB + FOLD_BLOCKS, 256>>>(p0, b2, fcw, out);
    accum_kernel<<<ACC_CHUNKS * BATCH, ACC_THREADS>>>(x, out);
}